// round 8
// baseline (speedup 1.0000x reference)
#include <cuda_runtime.h>
#include <cuda_fp16.h>
#include <math.h>

#define N_MAX 100000
#define E_MAX 3200000
#define SCAN_TPB 512
#define SCAN_NB ((N_MAX + SCAN_TPB - 1) / SCAN_TPB)

// ---- device scratch (allocation-free rule: static globals) ----
__device__ int     g_deg[N_MAX];
__device__ int     g_off[N_MAX + 1];
__device__ int     g_cur[N_MAX];
__device__ float   g_dinv[N_MAX];
__device__ float   g_t0[N_MAX];
__device__ float   g_acc1[N_MAX];           // layer-1 scalar scatter accumulator
__device__ int     g_srcs[E_MAX];
__device__ __half2 g_t1[N_MAX * 8];         // fp16 t1: 16 halves/node (32 B/row)
__device__ float4  g_bufB[N_MAX * 16];      // fp32: g (d16) and t4 stage (d5 pad8)
__device__ __half2 g_bufH[N_MAX * 32];      // fp16 t3: 64 halves/node (128 B/row)
__device__ int     g_bsum[SCAN_NB];

// accumulate a uint4 of 8 halves into fp32 acc[8]
__device__ __forceinline__ void hacc8(float* acc, uint4 hv) {
    float2 f0 = __half22float2(*(const __half2*)&hv.x);
    float2 f1 = __half22float2(*(const __half2*)&hv.y);
    float2 f2 = __half22float2(*(const __half2*)&hv.z);
    float2 f3 = __half22float2(*(const __half2*)&hv.w);
    acc[0] += f0.x; acc[1] += f0.y; acc[2] += f1.x; acc[3] += f1.y;
    acc[4] += f2.x; acc[5] += f2.y; acc[6] += f3.x; acc[7] += f3.y;
}

// ---------------- CSR build ----------------
__global__ void k_zero(int n) {
    int i = blockIdx.x * blockDim.x + threadIdx.x;
    if (i < n) { g_deg[i] = 0; g_acc1[i] = 0.0f; }
}

__global__ void k_count(const int* __restrict__ ei, int E) {
    int e = blockIdx.x * blockDim.x + threadIdx.x;
    if (e < E) atomicAdd(&g_deg[ei[E + e]], 1);
}

// vectorized: 4 dsts per thread (requires E % 4 == 0); ei pre-offset to dst half
__global__ void k_count4(const int* __restrict__ ei, int E4) {
    int e = blockIdx.x * blockDim.x + threadIdx.x;
    if (e < E4) {
        int4 d = ((const int4*)ei)[e];
        atomicAdd(&g_deg[d.x], 1);
        atomicAdd(&g_deg[d.y], 1);
        atomicAdd(&g_deg[d.z], 1);
        atomicAdd(&g_deg[d.w], 1);
    }
}

__global__ void k_scan1(int n) {
    __shared__ int sd[SCAN_TPB];
    int t = threadIdx.x;
    int i = blockIdx.x * SCAN_TPB + t;
    int v = (i < n) ? g_deg[i] : 0;
    sd[t] = v;
    __syncthreads();
    for (int off = 1; off < SCAN_TPB; off <<= 1) {
        int x = (t >= off) ? sd[t - off] : 0;
        __syncthreads();
        sd[t] += x;
        __syncthreads();
    }
    if (i < n) g_off[i] = sd[t] - v;
    if (t == SCAN_TPB - 1) g_bsum[blockIdx.x] = sd[t];
}

__global__ void k_scan2(int nb) {
    __shared__ int sd[256];
    int t = threadIdx.x;
    int v = (t < nb) ? g_bsum[t] : 0;
    sd[t] = v;
    __syncthreads();
    for (int off = 1; off < 256; off <<= 1) {
        int x = (t >= off) ? sd[t - off] : 0;
        __syncthreads();
        sd[t] += x;
        __syncthreads();
    }
    if (t < nb) g_bsum[t] = sd[t] - v;
}

// also computes dinv and t0 = x * dinv (layer-1 pre-scale)
__global__ void k_scan3(const float* __restrict__ x, int n, int E) {
    int i = blockIdx.x * blockDim.x + threadIdx.x;
    if (i < n) {
        int off = g_off[i] + g_bsum[i / SCAN_TPB];
        g_off[i] = off;
        g_cur[i] = off;
        float dv = rsqrtf((float)(g_deg[i] + 1));   // +1 self loop
        g_dinv[i] = dv;
        g_t0[i] = x[i] * dv;
        if (i == 0) g_off[n] = E;
    }
}

// fill CSR + fused layer-1 scalar scatter: acc1[d] += t0[s]
__global__ void k_fill(const int* __restrict__ ei, int E) {
    int e = blockIdx.x * blockDim.x + threadIdx.x;
    if (e < E) {
        int s = ei[e];
        int d = ei[E + e];
        int p = atomicAdd(&g_cur[d], 1);
        g_srcs[p] = s;
        atomicAdd(&g_acc1[d], __ldg(&g_t0[s]));
    }
}

// vectorized: 4 edges per thread (requires E % 4 == 0)
__global__ void k_fill4(const int* __restrict__ ei, int E, int E4) {
    int e = blockIdx.x * blockDim.x + threadIdx.x;
    if (e < E4) {
        int4 s = ((const int4*)ei)[e];
        int4 d = ((const int4*)(ei + E))[e];
        float t0x = __ldg(&g_t0[s.x]);
        float t0y = __ldg(&g_t0[s.y]);
        float t0z = __ldg(&g_t0[s.z]);
        float t0w = __ldg(&g_t0[s.w]);
        g_srcs[atomicAdd(&g_cur[d.x], 1)] = s.x;
        g_srcs[atomicAdd(&g_cur[d.y], 1)] = s.y;
        g_srcs[atomicAdd(&g_cur[d.z], 1)] = s.z;
        g_srcs[atomicAdd(&g_cur[d.w], 1)] = s.w;
        atomicAdd(&g_acc1[d.x], t0x);
        atomicAdd(&g_acc1[d.y], t0y);
        atomicAdd(&g_acc1[d.z], t0z);
        atomicAdd(&g_acc1[d.w], t0w);
    }
}

// ---------------- layer-1 node transform (no edge loop): t1 = fp16(dinv*relu(a*W1+b1)) ----------------
__global__ void k_l1n(const float* __restrict__ W1, const float* __restrict__ b1, int n) {
    __shared__ float sw[16], sb[16];
    if (threadIdx.x < 16) { sw[threadIdx.x] = W1[threadIdx.x]; sb[threadIdx.x] = b1[threadIdx.x]; }
    __syncthreads();
    int v = blockIdx.x * blockDim.x + threadIdx.x;
    if (v >= n) return;
    float dv = g_dinv[v];
    float a = (g_acc1[v] + g_t0[v]) * dv;
#pragma unroll
    for (int k = 0; k < 8; k++) {
        float u0 = dv * fmaxf(fmaf(a, sw[2 * k + 0], sb[2 * k + 0]), 0.f);
        float u1 = dv * fmaxf(fmaf(a, sw[2 * k + 1], sb[2 * k + 1]), 0.f);
        g_t1[v * 8 + k] = __float22half2_rn(make_float2(u0, u1));
    }
}

// ---------------- layer-2 agg d16 fp16, batch-8 MLP: g = dinv*(t1[v] + sum t1[src]) -> bufB fp32 ----------------
// 2 lanes per node; lane c owns one uint4 (16 B). Row = 32 B (full sector).
__global__ void k_agg2(int n) {
    int gid = blockIdx.x * blockDim.x + threadIdx.x;
    int v = gid >> 1;
    int c = gid & 1;
    if (v >= n) return;
    const uint4* tp = (const uint4*)g_t1;   // 2 uint4 per row
    float acc[8];
    {
        uint4 hv = tp[v * 2 + c];
        float2 f0 = __half22float2(*(const __half2*)&hv.x);
        float2 f1 = __half22float2(*(const __half2*)&hv.y);
        float2 f2 = __half22float2(*(const __half2*)&hv.z);
        float2 f3 = __half22float2(*(const __half2*)&hv.w);
        acc[0] = f0.x; acc[1] = f0.y; acc[2] = f1.x; acc[3] = f1.y;
        acc[4] = f2.x; acc[5] = f2.y; acc[6] = f3.x; acc[7] = f3.y;
    }
    int e = g_off[v], e1 = g_off[v + 1];
    for (; e + 8 <= e1; e += 8) {
        int s0 = __ldg(&g_srcs[e + 0]);
        int s1 = __ldg(&g_srcs[e + 1]);
        int s2 = __ldg(&g_srcs[e + 2]);
        int s3 = __ldg(&g_srcs[e + 3]);
        int s4 = __ldg(&g_srcs[e + 4]);
        int s5 = __ldg(&g_srcs[e + 5]);
        int s6 = __ldg(&g_srcs[e + 6]);
        int s7 = __ldg(&g_srcs[e + 7]);
        uint4 a0 = __ldg(&tp[s0 * 2 + c]);
        uint4 a1 = __ldg(&tp[s1 * 2 + c]);
        uint4 a2 = __ldg(&tp[s2 * 2 + c]);
        uint4 a3 = __ldg(&tp[s3 * 2 + c]);
        uint4 a4 = __ldg(&tp[s4 * 2 + c]);
        uint4 a5 = __ldg(&tp[s5 * 2 + c]);
        uint4 a6 = __ldg(&tp[s6 * 2 + c]);
        uint4 a7 = __ldg(&tp[s7 * 2 + c]);
        hacc8(acc, a0); hacc8(acc, a1); hacc8(acc, a2); hacc8(acc, a3);
        hacc8(acc, a4); hacc8(acc, a5); hacc8(acc, a6); hacc8(acc, a7);
    }
    for (; e < e1; e++) {
        int s = __ldg(&g_srcs[e]);
        hacc8(acc, __ldg(&tp[s * 2 + c]));
    }
    float dv = g_dinv[v];
    g_bufB[v * 4 + c * 2 + 0] = make_float4(acc[0] * dv, acc[1] * dv, acc[2] * dv, acc[3] * dv);
    g_bufB[v * 4 + c * 2 + 1] = make_float4(acc[4] * dv, acc[5] * dv, acc[6] * dv, acc[7] * dv);
}

// ---------------- fused W2 + relu + W3 + dinv, 2 nodes/thread: g(d16) -> t3(d64 fp16) ----------------
__global__ __launch_bounds__(128) void k_t23(const float* __restrict__ W2,
                                             const float* __restrict__ b2,
                                             const float* __restrict__ W3, int n) {
    __shared__ float sW2[16 * 64];
    __shared__ float sW3[64 * 64];
    __shared__ float sb2[64];
    int t = threadIdx.x;
    for (int i = t; i < 16 * 64; i += blockDim.x) sW2[i] = W2[i];
    for (int i = t; i < 64 * 64; i += blockDim.x) sW3[i] = W3[i];
    if (t < 64) sb2[t] = b2[t];
    __syncthreads();
    int vA = (blockIdx.x * blockDim.x + t) * 2;
    if (vA >= n) return;
    int vB = (vA + 1 < n) ? vA + 1 : vA;
    float gA[16], gB[16];
#pragma unroll
    for (int j = 0; j < 4; j++) {
        float4 ga = g_bufB[vA * 4 + j];
        float4 gb = g_bufB[vB * 4 + j];
        gA[4 * j] = ga.x; gA[4 * j + 1] = ga.y; gA[4 * j + 2] = ga.z; gA[4 * j + 3] = ga.w;
        gB[4 * j] = gb.x; gB[4 * j + 1] = gb.y; gB[4 * j + 2] = gb.z; gB[4 * j + 3] = gb.w;
    }
    float dvA = g_dinv[vA], dvB = g_dinv[vB];
#pragma unroll
    for (int h = 0; h < 2; h++) {
        float4 zA[8], zB[8];
#pragma unroll
        for (int j = 0; j < 8; j++) {
            zA[j] = make_float4(0.f, 0.f, 0.f, 0.f);
            zB[j] = make_float4(0.f, 0.f, 0.f, 0.f);
        }
#pragma unroll
        for (int tl = 0; tl < 4; tl++) {
            // y-tile = relu(g W2 + b2) for 16 i's, both nodes
            float4 yA4[4], yB4[4];
#pragma unroll
            for (int q = 0; q < 4; q++) {
                float4 bb = ((const float4*)sb2)[tl * 4 + q];
                yA4[q] = bb; yB4[q] = bb;
            }
#pragma unroll
            for (int k = 0; k < 16; k++) {
                const float4* wk = (const float4*)&sW2[k * 64 + tl * 16];
                float ak = gA[k], bk = gB[k];
#pragma unroll
                for (int q = 0; q < 4; q++) {
                    float4 w = wk[q];
                    yA4[q].x = fmaf(ak, w.x, yA4[q].x); yA4[q].y = fmaf(ak, w.y, yA4[q].y);
                    yA4[q].z = fmaf(ak, w.z, yA4[q].z); yA4[q].w = fmaf(ak, w.w, yA4[q].w);
                    yB4[q].x = fmaf(bk, w.x, yB4[q].x); yB4[q].y = fmaf(bk, w.y, yB4[q].y);
                    yB4[q].z = fmaf(bk, w.z, yB4[q].z); yB4[q].w = fmaf(bk, w.w, yB4[q].w);
                }
            }
            float yAs[16], yBs[16];
#pragma unroll
            for (int q = 0; q < 4; q++) {
                yAs[4 * q + 0] = fmaxf(yA4[q].x, 0.f); yAs[4 * q + 1] = fmaxf(yA4[q].y, 0.f);
                yAs[4 * q + 2] = fmaxf(yA4[q].z, 0.f); yAs[4 * q + 3] = fmaxf(yA4[q].w, 0.f);
                yBs[4 * q + 0] = fmaxf(yB4[q].x, 0.f); yBs[4 * q + 1] = fmaxf(yB4[q].y, 0.f);
                yBs[4 * q + 2] = fmaxf(yB4[q].z, 0.f); yBs[4 * q + 3] = fmaxf(yB4[q].w, 0.f);
            }
#pragma unroll
            for (int ii = 0; ii < 16; ii++) {
                const float4* wr = (const float4*)&sW3[(tl * 16 + ii) * 64 + h * 32];
                float ya = yAs[ii], yb = yBs[ii];
#pragma unroll
                for (int j = 0; j < 8; j++) {
                    float4 w = wr[j];
                    zA[j].x = fmaf(ya, w.x, zA[j].x); zA[j].y = fmaf(ya, w.y, zA[j].y);
                    zA[j].z = fmaf(ya, w.z, zA[j].z); zA[j].w = fmaf(ya, w.w, zA[j].w);
                    zB[j].x = fmaf(yb, w.x, zB[j].x); zB[j].y = fmaf(yb, w.y, zB[j].y);
                    zB[j].z = fmaf(yb, w.z, zB[j].z); zB[j].w = fmaf(yb, w.w, zB[j].w);
                }
            }
        }
#pragma unroll
        for (int j = 0; j < 8; j++) {
            g_bufH[vA * 32 + h * 16 + j * 2 + 0] = __float22half2_rn(make_float2(zA[j].x * dvA, zA[j].y * dvA));
            g_bufH[vA * 32 + h * 16 + j * 2 + 1] = __float22half2_rn(make_float2(zA[j].z * dvA, zA[j].w * dvA));
            g_bufH[vB * 32 + h * 16 + j * 2 + 0] = __float22half2_rn(make_float2(zB[j].x * dvB, zB[j].y * dvB));
            g_bufH[vB * 32 + h * 16 + j * 2 + 1] = __float22half2_rn(make_float2(zB[j].z * dvB, zB[j].w * dvB));
        }
    }
}

// ---------------- d=64 fp16 agg (batch-8 MLP) + b3 + relu + W4 + group reduce + dinv ----------------
// 8 lanes per node; lane c owns one uint4 (16 B). Row = 128 B (full line).
__global__ void k_agg3w4(const float* __restrict__ b3, const float* __restrict__ W4, int n) {
    __shared__ float sW4[64 * 5];
    int t = threadIdx.x;
    for (int i = t; i < 64 * 5; i += blockDim.x) sW4[i] = W4[i];
    __syncthreads();
    int gid = blockIdx.x * blockDim.x + t;
    int v = gid / 8;
    int c = gid % 8;
    if (v >= n) return;

    const uint4* hp = (const uint4*)g_bufH;   // 8 uint4 per node row
    float acc[8];
    {
        uint4 hv = hp[v * 8 + c];             // self-loop term
        float2 f0 = __half22float2(*(const __half2*)&hv.x);
        float2 f1 = __half22float2(*(const __half2*)&hv.y);
        float2 f2 = __half22float2(*(const __half2*)&hv.z);
        float2 f3 = __half22float2(*(const __half2*)&hv.w);
        acc[0] = f0.x; acc[1] = f0.y; acc[2] = f1.x; acc[3] = f1.y;
        acc[4] = f2.x; acc[5] = f2.y; acc[6] = f3.x; acc[7] = f3.y;
    }
    int e = g_off[v], e1 = g_off[v + 1];
    for (; e + 8 <= e1; e += 8) {
        int s0 = __ldg(&g_srcs[e + 0]);
        int s1 = __ldg(&g_srcs[e + 1]);
        int s2 = __ldg(&g_srcs[e + 2]);
        int s3 = __ldg(&g_srcs[e + 3]);
        int s4 = __ldg(&g_srcs[e + 4]);
        int s5 = __ldg(&g_srcs[e + 5]);
        int s6 = __ldg(&g_srcs[e + 6]);
        int s7 = __ldg(&g_srcs[e + 7]);
        uint4 a0 = __ldg(&hp[s0 * 8 + c]);
        uint4 a1 = __ldg(&hp[s1 * 8 + c]);
        uint4 a2 = __ldg(&hp[s2 * 8 + c]);
        uint4 a3 = __ldg(&hp[s3 * 8 + c]);
        uint4 a4 = __ldg(&hp[s4 * 8 + c]);
        uint4 a5 = __ldg(&hp[s5 * 8 + c]);
        uint4 a6 = __ldg(&hp[s6 * 8 + c]);
        uint4 a7 = __ldg(&hp[s7 * 8 + c]);
        hacc8(acc, a0); hacc8(acc, a1); hacc8(acc, a2); hacc8(acc, a3);
        hacc8(acc, a4); hacc8(acc, a5); hacc8(acc, a6); hacc8(acc, a7);
    }
    for (; e < e1; e++) {
        int s = __ldg(&g_srcs[e]);
        hacc8(acc, __ldg(&hp[s * 8 + c]));
    }
    float dv = g_dinv[v];
    float4 bb0 = ((const float4*)b3)[2 * c];
    float4 bb1 = ((const float4*)b3)[2 * c + 1];
    float h[8];
    h[0] = fmaxf(fmaf(acc[0], dv, bb0.x), 0.f);
    h[1] = fmaxf(fmaf(acc[1], dv, bb0.y), 0.f);
    h[2] = fmaxf(fmaf(acc[2], dv, bb0.z), 0.f);
    h[3] = fmaxf(fmaf(acc[3], dv, bb0.w), 0.f);
    h[4] = fmaxf(fmaf(acc[4], dv, bb1.x), 0.f);
    h[5] = fmaxf(fmaf(acc[5], dv, bb1.y), 0.f);
    h[6] = fmaxf(fmaf(acc[6], dv, bb1.z), 0.f);
    h[7] = fmaxf(fmaf(acc[7], dv, bb1.w), 0.f);
    const float* w = &sW4[c * 8 * 5];
    float p[5];
#pragma unroll
    for (int j = 0; j < 5; j++) {
        float s = h[0] * w[j];
#pragma unroll
        for (int i = 1; i < 8; i++) s = fmaf(h[i], w[i * 5 + j], s);
        p[j] = s;
    }
    unsigned m = __activemask();
#pragma unroll
    for (int off = 4; off > 0; off >>= 1) {
#pragma unroll
        for (int j = 0; j < 5; j++) p[j] += __shfl_down_sync(m, p[j], off, 8);
    }
    if (c == 0) {
        g_bufB[v * 2 + 0] = make_float4(dv * p[0], dv * p[1], dv * p[2], dv * p[3]);
        g_bufB[v * 2 + 1] = make_float4(dv * p[4], 0.f, 0.f, 0.f);
    }
}

// ---------------- final d=5 agg + b4 + log_softmax ----------------
__global__ void k_final(const float* __restrict__ b4, float* __restrict__ out, int n) {
    int v = blockIdx.x * blockDim.x + threadIdx.x;
    if (v >= n) return;
    float4 a0 = g_bufB[v * 2 + 0];
    float4 a1 = g_bufB[v * 2 + 1];
    int e = g_off[v], e1 = g_off[v + 1];
#pragma unroll 4
    for (; e < e1; e++) {
        int s = __ldg(&g_srcs[e]);
        float4 t0 = __ldg(&g_bufB[s * 2 + 0]);
        float4 t1 = __ldg(&g_bufB[s * 2 + 1]);
        a0.x += t0.x; a0.y += t0.y; a0.z += t0.z; a0.w += t0.w;
        a1.x += t1.x;
    }
    float dv = g_dinv[v];
    float z[5];
    z[0] = fmaf(a0.x, dv, b4[0]);
    z[1] = fmaf(a0.y, dv, b4[1]);
    z[2] = fmaf(a0.z, dv, b4[2]);
    z[3] = fmaf(a0.w, dv, b4[3]);
    z[4] = fmaf(a1.x, dv, b4[4]);
    float mx = z[0];
#pragma unroll
    for (int j = 1; j < 5; j++) mx = fmaxf(mx, z[j]);
    float sum = 0.f;
#pragma unroll
    for (int j = 0; j < 5; j++) sum += expf(z[j] - mx);
    float l = mx + logf(sum);
#pragma unroll
    for (int j = 0; j < 5; j++) out[v * 5 + j] = z[j] - l;
}

extern "C" void kernel_launch(void* const* d_in, const int* in_sizes, int n_in,
                              void* d_out, int out_size) {
    const float* x  = (const float*)d_in[0];
    const int*   ei = (const int*)d_in[1];      // int32 (JAX x64 disabled)
    const float* W1 = (const float*)d_in[2];
    const float* b1 = (const float*)d_in[3];
    const float* W2 = (const float*)d_in[4];
    const float* b2 = (const float*)d_in[5];
    const float* W3 = (const float*)d_in[6];
    const float* b3 = (const float*)d_in[7];
    const float* W4 = (const float*)d_in[8];
    const float* b4 = (const float*)d_in[9];
    float* out = (float*)d_out;

    int N = in_sizes[0];
    int E = in_sizes[1] / 2;

    int nB  = (N + 255) / 256;
    int snb = (N + SCAN_TPB - 1) / SCAN_TPB;

    // CSR build (+ fused layer-1 scalar scatter in fill)
    k_zero<<<nB, 256>>>(N);
    if ((E & 3) == 0) {
        int E4 = E >> 2;
        int eB4 = (E4 + 255) / 256;
        k_count4<<<eB4, 256>>>(ei + E, E4);
        k_scan1<<<snb, SCAN_TPB>>>(N);
        k_scan2<<<1, 256>>>(snb);
        k_scan3<<<nB, 256>>>(x, N, E);
        k_fill4<<<eB4, 256>>>(ei, E, E4);
    } else {
        int eB = (E + 255) / 256;
        k_count<<<eB, 256>>>(ei, E);
        k_scan1<<<snb, SCAN_TPB>>>(N);
        k_scan2<<<1, 256>>>(snb);
        k_scan3<<<nB, 256>>>(x, N, E);
        k_fill<<<eB, 256>>>(ei, E);
    }

    // Layer 1 node transform (agg was fused into fill as scatter)
    k_l1n<<<nB, 256>>>(W1, b1, N);
    // Layer 2 agg in d=16 fp16 (before W2), batch-8 MLP
    k_agg2<<<(N * 2 + 255) / 256, 256>>>(N);
    // Fused W2+relu+W3 node transform, 2 nodes/thread
    {
        int n2 = (N + 1) / 2;
        k_t23<<<(n2 + 127) / 128, 128>>>(W2, b2, W3, N);
    }
    // Layer 3 agg d=64 fp16 (batch-8 MLP), fused bias/relu/W4 epilogue
    k_agg3w4<<<(N * 8 + 255) / 256, 256>>>(b3, W4, N);
    // Layer 4 agg d=5 + log_softmax
    k_final<<<nB, 256>>>(b4, out, N);
}

// round 9
// speedup vs baseline: 1.1975x; 1.1975x over previous
#include <cuda_runtime.h>
#include <cuda_fp16.h>
#include <math.h>

#define N_MAX 100000
#define E_MAX 3200000
#define SCAN_TPB 512
#define SCAN_NB ((N_MAX + SCAN_TPB - 1) / SCAN_TPB)

// ---- device scratch (allocation-free rule: static globals) ----
__device__ int     g_deg[N_MAX];
__device__ int     g_off[N_MAX + 1];
__device__ int     g_cur[N_MAX];
__device__ float   g_dinv[N_MAX];
__device__ float   g_t0[N_MAX];
__device__ int     g_srcs[E_MAX];
__device__ __half2 g_t1[N_MAX * 8];         // fp16 t1: 16 halves/node (32 B/row)
__device__ float4  g_bufB[N_MAX * 16];      // fp32: g (d16) and t4 stage (d5 pad8)
__device__ __half2 g_bufH[N_MAX * 32];      // fp16 t3: 64 halves/node (128 B/row)
__device__ unsigned long long g_pack[SCAN_NB];  // decoupled-lookback: bit63 flag | low32 block sum

// accumulate a uint4 of 8 halves into fp32 acc[8]
__device__ __forceinline__ void hacc8(float* acc, uint4 hv) {
    float2 f0 = __half22float2(*(const __half2*)&hv.x);
    float2 f1 = __half22float2(*(const __half2*)&hv.y);
    float2 f2 = __half22float2(*(const __half2*)&hv.z);
    float2 f3 = __half22float2(*(const __half2*)&hv.w);
    acc[0] += f0.x; acc[1] += f0.y; acc[2] += f1.x; acc[3] += f1.y;
    acc[4] += f2.x; acc[5] += f2.y; acc[6] += f3.x; acc[7] += f3.y;
}

// ---------------- CSR build ----------------
__global__ void k_zero(int n) {
    int i = blockIdx.x * blockDim.x + threadIdx.x;
    if (i < n) g_deg[i] = 0;
    if (i < SCAN_NB) g_pack[i] = 0ULL;
}

__global__ void k_count(const int* __restrict__ ei, int E) {
    int e = blockIdx.x * blockDim.x + threadIdx.x;
    if (e < E) atomicAdd(&g_deg[ei[E + e]], 1);
}

// vectorized: 4 dsts per thread (requires E % 4 == 0); ei pre-offset to dst half
__global__ void k_count4(const int* __restrict__ ei, int E4) {
    int e = blockIdx.x * blockDim.x + threadIdx.x;
    if (e < E4) {
        int4 d = ((const int4*)ei)[e];
        atomicAdd(&g_deg[d.x], 1);
        atomicAdd(&g_deg[d.y], 1);
        atomicAdd(&g_deg[d.z], 1);
        atomicAdd(&g_deg[d.w], 1);
    }
}

// ---- fused single-pass exclusive scan (decoupled lookback) + dinv + t0 ----
// replaces scan1+scan2+scan3. All SCAN_NB blocks are co-resident (196 blocks,
// 512 thr: >= 4 blocks/SM * 148 SMs capacity), so spin-wait cannot deadlock.
__global__ __launch_bounds__(SCAN_TPB) void k_scanf(const float* __restrict__ x, int n, int E) {
    __shared__ int sd[SCAN_TPB];
    int t = threadIdx.x;
    int b = blockIdx.x;
    int i = b * SCAN_TPB + t;
    int v = (i < n) ? g_deg[i] : 0;
    sd[t] = v;
    __syncthreads();
    for (int off = 1; off < SCAN_TPB; off <<= 1) {
        int y = (t >= off) ? sd[t - off] : 0;
        __syncthreads();
        sd[t] += y;
        __syncthreads();
    }
    int incl = sd[t];                       // inclusive prefix within block
    // publish block aggregate (flag|value in one 64-bit word: atomic by location)
    if (t == SCAN_TPB - 1) {
        unsigned long long p = (1ULL << 63) | (unsigned long long)(unsigned)incl;
        *((volatile unsigned long long*)&g_pack[b]) = p;
    }
    // lookback: sum aggregates of all prior blocks (parallel across threads)
    int offs = 0;
    for (int p = t; p < b; p += SCAN_TPB) {
        unsigned long long w;
        do { w = *((volatile unsigned long long*)&g_pack[p]); } while (!(w >> 63));
        offs += (int)(unsigned)(w & 0xFFFFFFFFULL);
    }
    __syncthreads();                        // sd free for reuse
    sd[t] = offs;
    __syncthreads();
    for (int o = SCAN_TPB / 2; o > 0; o >>= 1) {
        if (t < o) sd[t] += sd[t + o];
        __syncthreads();
    }
    int blockoff = sd[0];
    if (i < n) {
        int off = blockoff + incl - v;      // global exclusive prefix
        g_off[i] = off;
        g_cur[i] = off;
        float dv = rsqrtf((float)(v + 1));  // +1 self loop
        g_dinv[i] = dv;
        g_t0[i] = x[i] * dv;
        if (i == 0) g_off[n] = E;
    }
}

__global__ void k_fill(const int* __restrict__ ei, int E) {
    int e = blockIdx.x * blockDim.x + threadIdx.x;
    if (e < E) {
        int s = ei[e];
        int d = ei[E + e];
        int p = atomicAdd(&g_cur[d], 1);
        g_srcs[p] = s;
    }
}

// vectorized: 4 edges per thread (requires E % 4 == 0)
__global__ void k_fill4(const int* __restrict__ ei, int E, int E4) {
    int e = blockIdx.x * blockDim.x + threadIdx.x;
    if (e < E4) {
        int4 s = ((const int4*)ei)[e];
        int4 d = ((const int4*)(ei + E))[e];
        g_srcs[atomicAdd(&g_cur[d.x], 1)] = s.x;
        g_srcs[atomicAdd(&g_cur[d.y], 1)] = s.y;
        g_srcs[atomicAdd(&g_cur[d.z], 1)] = s.z;
        g_srcs[atomicAdd(&g_cur[d.w], 1)] = s.w;
    }
}

// ---------------- layer 1: scalar agg of t0, then t1 = fp16(dinv*relu(a*W1+b1)) ----------------
__global__ void k_l1(const float* __restrict__ W1, const float* __restrict__ b1, int n) {
    __shared__ float sw[16], sb[16];
    if (threadIdx.x < 16) { sw[threadIdx.x] = W1[threadIdx.x]; sb[threadIdx.x] = b1[threadIdx.x]; }
    __syncthreads();
    int v = blockIdx.x * blockDim.x + threadIdx.x;
    if (v >= n) return;
    float a = g_t0[v];
    int e = g_off[v], e1 = g_off[v + 1];
#pragma unroll 4
    for (; e < e1; e++) a += __ldg(&g_t0[__ldg(&g_srcs[e])]);
    float dv = g_dinv[v];
    a *= dv;
#pragma unroll
    for (int k = 0; k < 8; k++) {
        float u0 = dv * fmaxf(fmaf(a, sw[2 * k + 0], sb[2 * k + 0]), 0.f);
        float u1 = dv * fmaxf(fmaf(a, sw[2 * k + 1], sb[2 * k + 1]), 0.f);
        g_t1[v * 8 + k] = __float22half2_rn(make_float2(u0, u1));
    }
}

// ---------------- layer-2 agg d16 fp16, batch-8 MLP: g = dinv*(t1[v] + sum t1[src]) -> bufB fp32 ----------------
// 2 lanes per node; lane c owns one uint4 (16 B). Row = 32 B (full sector).
__global__ void k_agg2(int n) {
    int gid = blockIdx.x * blockDim.x + threadIdx.x;
    int v = gid >> 1;
    int c = gid & 1;
    if (v >= n) return;
    const uint4* tp = (const uint4*)g_t1;   // 2 uint4 per row
    float acc[8];
    {
        uint4 hv = tp[v * 2 + c];
        float2 f0 = __half22float2(*(const __half2*)&hv.x);
        float2 f1 = __half22float2(*(const __half2*)&hv.y);
        float2 f2 = __half22float2(*(const __half2*)&hv.z);
        float2 f3 = __half22float2(*(const __half2*)&hv.w);
        acc[0] = f0.x; acc[1] = f0.y; acc[2] = f1.x; acc[3] = f1.y;
        acc[4] = f2.x; acc[5] = f2.y; acc[6] = f3.x; acc[7] = f3.y;
    }
    int e = g_off[v], e1 = g_off[v + 1];
    for (; e + 8 <= e1; e += 8) {
        int s0 = __ldg(&g_srcs[e + 0]);
        int s1 = __ldg(&g_srcs[e + 1]);
        int s2 = __ldg(&g_srcs[e + 2]);
        int s3 = __ldg(&g_srcs[e + 3]);
        int s4 = __ldg(&g_srcs[e + 4]);
        int s5 = __ldg(&g_srcs[e + 5]);
        int s6 = __ldg(&g_srcs[e + 6]);
        int s7 = __ldg(&g_srcs[e + 7]);
        uint4 a0 = __ldg(&tp[s0 * 2 + c]);
        uint4 a1 = __ldg(&tp[s1 * 2 + c]);
        uint4 a2 = __ldg(&tp[s2 * 2 + c]);
        uint4 a3 = __ldg(&tp[s3 * 2 + c]);
        uint4 a4 = __ldg(&tp[s4 * 2 + c]);
        uint4 a5 = __ldg(&tp[s5 * 2 + c]);
        uint4 a6 = __ldg(&tp[s6 * 2 + c]);
        uint4 a7 = __ldg(&tp[s7 * 2 + c]);
        hacc8(acc, a0); hacc8(acc, a1); hacc8(acc, a2); hacc8(acc, a3);
        hacc8(acc, a4); hacc8(acc, a5); hacc8(acc, a6); hacc8(acc, a7);
    }
    for (; e < e1; e++) {
        int s = __ldg(&g_srcs[e]);
        hacc8(acc, __ldg(&tp[s * 2 + c]));
    }
    float dv = g_dinv[v];
    g_bufB[v * 4 + c * 2 + 0] = make_float4(acc[0] * dv, acc[1] * dv, acc[2] * dv, acc[3] * dv);
    g_bufB[v * 4 + c * 2 + 1] = make_float4(acc[4] * dv, acc[5] * dv, acc[6] * dv, acc[7] * dv);
}

// ---------------- fused W2 + relu + W3 + dinv (R7 version, 1 node/thread): g(d16) -> t3(d64 fp16) ----------------
__global__ __launch_bounds__(128) void k_t23(const float* __restrict__ W2,
                                             const float* __restrict__ b2,
                                             const float* __restrict__ W3, int n) {
    __shared__ float sW2[16 * 64];
    __shared__ float sW3[64 * 64];
    __shared__ float sb2[64];
    int t = threadIdx.x;
    for (int i = t; i < 16 * 64; i += blockDim.x) sW2[i] = W2[i];
    for (int i = t; i < 64 * 64; i += blockDim.x) sW3[i] = W3[i];
    if (t < 64) sb2[t] = b2[t];
    __syncthreads();
    int v = blockIdx.x * blockDim.x + t;
    if (v >= n) return;
    float g[16];
#pragma unroll
    for (int j = 0; j < 4; j++) {
        float4 gg = g_bufB[v * 4 + j];
        g[4 * j] = gg.x; g[4 * j + 1] = gg.y; g[4 * j + 2] = gg.z; g[4 * j + 3] = gg.w;
    }
    // y = relu(g W2 + b2)
    float y[64];
#pragma unroll
    for (int jj = 0; jj < 16; jj++) {
        float4 a = ((const float4*)sb2)[jj];
#pragma unroll
        for (int i = 0; i < 16; i++) {
            float4 w = ((const float4*)&sW2[i * 64])[jj];
            a.x = fmaf(g[i], w.x, a.x); a.y = fmaf(g[i], w.y, a.y);
            a.z = fmaf(g[i], w.z, a.z); a.w = fmaf(g[i], w.w, a.w);
        }
        y[4 * jj]     = fmaxf(a.x, 0.f);
        y[4 * jj + 1] = fmaxf(a.y, 0.f);
        y[4 * jj + 2] = fmaxf(a.z, 0.f);
        y[4 * jj + 3] = fmaxf(a.w, 0.f);
    }
    // t3 = dinv * (y W3), two halves of 32 outputs, stored fp16
    float dv = g_dinv[v];
#pragma unroll
    for (int h = 0; h < 2; h++) {
        float4 z[8];
#pragma unroll
        for (int j = 0; j < 8; j++) z[j] = make_float4(0.f, 0.f, 0.f, 0.f);
#pragma unroll
        for (int i = 0; i < 64; i++) {
            float yi = y[i];
            const float4* wr = (const float4*)&sW3[i * 64 + h * 32];
#pragma unroll
            for (int j = 0; j < 8; j++) {
                float4 w = wr[j];
                z[j].x = fmaf(yi, w.x, z[j].x); z[j].y = fmaf(yi, w.y, z[j].y);
                z[j].z = fmaf(yi, w.z, z[j].z); z[j].w = fmaf(yi, w.w, z[j].w);
            }
        }
#pragma unroll
        for (int j = 0; j < 8; j++) {
            g_bufH[v * 32 + h * 16 + j * 2 + 0] =
                __float22half2_rn(make_float2(z[j].x * dv, z[j].y * dv));
            g_bufH[v * 32 + h * 16 + j * 2 + 1] =
                __float22half2_rn(make_float2(z[j].z * dv, z[j].w * dv));
        }
    }
}

// ---------------- d=64 fp16 agg (batch-8 MLP) + b3 + relu + W4 + group reduce + dinv ----------------
// 8 lanes per node; lane c owns one uint4 (16 B). Row = 128 B (full line).
__global__ void k_agg3w4(const float* __restrict__ b3, const float* __restrict__ W4, int n) {
    __shared__ float sW4[64 * 5];
    int t = threadIdx.x;
    for (int i = t; i < 64 * 5; i += blockDim.x) sW4[i] = W4[i];
    __syncthreads();
    int gid = blockIdx.x * blockDim.x + t;
    int v = gid / 8;
    int c = gid % 8;
    if (v >= n) return;

    const uint4* hp = (const uint4*)g_bufH;   // 8 uint4 per node row
    float acc[8];
    {
        uint4 hv = hp[v * 8 + c];             // self-loop term
        float2 f0 = __half22float2(*(const __half2*)&hv.x);
        float2 f1 = __half22float2(*(const __half2*)&hv.y);
        float2 f2 = __half22float2(*(const __half2*)&hv.z);
        float2 f3 = __half22float2(*(const __half2*)&hv.w);
        acc[0] = f0.x; acc[1] = f0.y; acc[2] = f1.x; acc[3] = f1.y;
        acc[4] = f2.x; acc[5] = f2.y; acc[6] = f3.x; acc[7] = f3.y;
    }
    int e = g_off[v], e1 = g_off[v + 1];
    for (; e + 8 <= e1; e += 8) {
        int s0 = __ldg(&g_srcs[e + 0]);
        int s1 = __ldg(&g_srcs[e + 1]);
        int s2 = __ldg(&g_srcs[e + 2]);
        int s3 = __ldg(&g_srcs[e + 3]);
        int s4 = __ldg(&g_srcs[e + 4]);
        int s5 = __ldg(&g_srcs[e + 5]);
        int s6 = __ldg(&g_srcs[e + 6]);
        int s7 = __ldg(&g_srcs[e + 7]);
        uint4 a0 = __ldg(&hp[s0 * 8 + c]);
        uint4 a1 = __ldg(&hp[s1 * 8 + c]);
        uint4 a2 = __ldg(&hp[s2 * 8 + c]);
        uint4 a3 = __ldg(&hp[s3 * 8 + c]);
        uint4 a4 = __ldg(&hp[s4 * 8 + c]);
        uint4 a5 = __ldg(&hp[s5 * 8 + c]);
        uint4 a6 = __ldg(&hp[s6 * 8 + c]);
        uint4 a7 = __ldg(&hp[s7 * 8 + c]);
        hacc8(acc, a0); hacc8(acc, a1); hacc8(acc, a2); hacc8(acc, a3);
        hacc8(acc, a4); hacc8(acc, a5); hacc8(acc, a6); hacc8(acc, a7);
    }
    for (; e < e1; e++) {
        int s = __ldg(&g_srcs[e]);
        hacc8(acc, __ldg(&hp[s * 8 + c]));
    }
    float dv = g_dinv[v];
    float4 bb0 = ((const float4*)b3)[2 * c];
    float4 bb1 = ((const float4*)b3)[2 * c + 1];
    float h[8];
    h[0] = fmaxf(fmaf(acc[0], dv, bb0.x), 0.f);
    h[1] = fmaxf(fmaf(acc[1], dv, bb0.y), 0.f);
    h[2] = fmaxf(fmaf(acc[2], dv, bb0.z), 0.f);
    h[3] = fmaxf(fmaf(acc[3], dv, bb0.w), 0.f);
    h[4] = fmaxf(fmaf(acc[4], dv, bb1.x), 0.f);
    h[5] = fmaxf(fmaf(acc[5], dv, bb1.y), 0.f);
    h[6] = fmaxf(fmaf(acc[6], dv, bb1.z), 0.f);
    h[7] = fmaxf(fmaf(acc[7], dv, bb1.w), 0.f);
    const float* w = &sW4[c * 8 * 5];
    float p[5];
#pragma unroll
    for (int j = 0; j < 5; j++) {
        float s = h[0] * w[j];
#pragma unroll
        for (int i = 1; i < 8; i++) s = fmaf(h[i], w[i * 5 + j], s);
        p[j] = s;
    }
    unsigned m = __activemask();
#pragma unroll
    for (int off = 4; off > 0; off >>= 1) {
#pragma unroll
        for (int j = 0; j < 5; j++) p[j] += __shfl_down_sync(m, p[j], off, 8);
    }
    if (c == 0) {
        g_bufB[v * 2 + 0] = make_float4(dv * p[0], dv * p[1], dv * p[2], dv * p[3]);
        g_bufB[v * 2 + 1] = make_float4(dv * p[4], 0.f, 0.f, 0.f);
    }
}

// ---------------- final d=5 agg + b4 + log_softmax ----------------
__global__ void k_final(const float* __restrict__ b4, float* __restrict__ out, int n) {
    int v = blockIdx.x * blockDim.x + threadIdx.x;
    if (v >= n) return;
    float4 a0 = g_bufB[v * 2 + 0];
    float4 a1 = g_bufB[v * 2 + 1];
    int e = g_off[v], e1 = g_off[v + 1];
#pragma unroll 4
    for (; e < e1; e++) {
        int s = __ldg(&g_srcs[e]);
        float4 t0 = __ldg(&g_bufB[s * 2 + 0]);
        float4 t1 = __ldg(&g_bufB[s * 2 + 1]);
        a0.x += t0.x; a0.y += t0.y; a0.z += t0.z; a0.w += t0.w;
        a1.x += t1.x;
    }
    float dv = g_dinv[v];
    float z[5];
    z[0] = fmaf(a0.x, dv, b4[0]);
    z[1] = fmaf(a0.y, dv, b4[1]);
    z[2] = fmaf(a0.z, dv, b4[2]);
    z[3] = fmaf(a0.w, dv, b4[3]);
    z[4] = fmaf(a1.x, dv, b4[4]);
    float mx = z[0];
#pragma unroll
    for (int j = 1; j < 5; j++) mx = fmaxf(mx, z[j]);
    float sum = 0.f;
#pragma unroll
    for (int j = 0; j < 5; j++) sum += expf(z[j] - mx);
    float l = mx + logf(sum);
#pragma unroll
    for (int j = 0; j < 5; j++) out[v * 5 + j] = z[j] - l;
}

extern "C" void kernel_launch(void* const* d_in, const int* in_sizes, int n_in,
                              void* d_out, int out_size) {
    const float* x  = (const float*)d_in[0];
    const int*   ei = (const int*)d_in[1];      // int32 (JAX x64 disabled)
    const float* W1 = (const float*)d_in[2];
    const float* b1 = (const float*)d_in[3];
    const float* W2 = (const float*)d_in[4];
    const float* b2 = (const float*)d_in[5];
    const float* W3 = (const float*)d_in[6];
    const float* b3 = (const float*)d_in[7];
    const float* W4 = (const float*)d_in[8];
    const float* b4 = (const float*)d_in[9];
    float* out = (float*)d_out;

    int N = in_sizes[0];
    int E = in_sizes[1] / 2;

    int nB  = (N + 255) / 256;
    int snb = (N + SCAN_TPB - 1) / SCAN_TPB;

    // CSR build: zero -> count -> fused scan -> fill
    k_zero<<<nB, 256>>>(N);
    if ((E & 3) == 0) {
        int E4 = E >> 2;
        int eB4 = (E4 + 255) / 256;
        k_count4<<<eB4, 256>>>(ei + E, E4);
        k_scanf<<<snb, SCAN_TPB>>>(x, N, E);
        k_fill4<<<eB4, 256>>>(ei, E, E4);
    } else {
        int eB = (E + 255) / 256;
        k_count<<<eB, 256>>>(ei, E);
        k_scanf<<<snb, SCAN_TPB>>>(x, N, E);
        k_fill<<<eB, 256>>>(ei, E);
    }

    // Layer 1: scalar agg + transform (1->16), fp16 out
    k_l1<<<nB, 256>>>(W1, b1, N);
    // Layer 2 agg in d=16 fp16 (before W2), batch-8 MLP
    k_agg2<<<(N * 2 + 255) / 256, 256>>>(N);
    // Fused W2+relu+W3 node transform (1 node/thread, no spills)
    k_t23<<<(N + 127) / 128, 128>>>(W2, b2, W3, N);
    // Layer 3 agg d=64 fp16 (batch-8 MLP), fused bias/relu/W4 epilogue
    k_agg3w4<<<(N * 8 + 255) / 256, 256>>>(b3, W4, N);
    // Layer 4 agg d=5 + log_softmax
    k_final<<<nB, 256>>>(b4, out, N);
}

// round 10
// speedup vs baseline: 1.2622x; 1.0540x over previous
#include <cuda_runtime.h>
#include <cuda_fp16.h>
#include <math.h>

#define N_MAX 100000
#define E_MAX 3200000
#define SCAN_TPB 512
#define SCAN_NB ((N_MAX + SCAN_TPB - 1) / SCAN_TPB)

// ---- device scratch (allocation-free rule: static globals) ----
__device__ int     g_deg[N_MAX];
__device__ int     g_off[N_MAX + 1];
__device__ float   g_dinv[N_MAX];
__device__ float   g_t0[N_MAX];
__device__ int     g_rank[E_MAX];           // per-edge rank within its dst (from count atomic)
__device__ int     g_srcs[E_MAX];
__device__ __half2 g_t1[N_MAX * 8];         // fp16 t1: 16 halves/node (32 B/row)
__device__ float4  g_bufB[N_MAX * 16];      // fp32: g (d16) and t4 stage (d5 pad8)
__device__ __half2 g_bufH[N_MAX * 32];      // fp16 t3: 64 halves/node (128 B/row)
__device__ unsigned long long g_pack[SCAN_NB];  // decoupled-lookback: bit63 flag | low32 sum

// accumulate a uint4 of 8 halves into fp32 acc[8]
__device__ __forceinline__ void hacc8(float* acc, uint4 hv) {
    float2 f0 = __half22float2(*(const __half2*)&hv.x);
    float2 f1 = __half22float2(*(const __half2*)&hv.y);
    float2 f2 = __half22float2(*(const __half2*)&hv.z);
    float2 f3 = __half22float2(*(const __half2*)&hv.w);
    acc[0] += f0.x; acc[1] += f0.y; acc[2] += f1.x; acc[3] += f1.y;
    acc[4] += f2.x; acc[5] += f2.y; acc[6] += f3.x; acc[7] += f3.y;
}

// ---------------- CSR build ----------------
__global__ void k_zero(int n) {
    int i = blockIdx.x * blockDim.x + threadIdx.x;
    if (i < n) g_deg[i] = 0;
    if (i < SCAN_NB) g_pack[i] = 0ULL;
}

// count + record rank of each edge within its dst
__global__ void k_count(const int* __restrict__ ei, int E) {
    int e = blockIdx.x * blockDim.x + threadIdx.x;
    if (e < E) g_rank[e] = atomicAdd(&g_deg[ei[E + e]], 1);
}

// vectorized: 4 dsts per thread (requires E % 4 == 0); ei pre-offset to dst half
__global__ void k_count4(const int* __restrict__ ei, int E4) {
    int e = blockIdx.x * blockDim.x + threadIdx.x;
    if (e < E4) {
        int4 d = ((const int4*)ei)[e];
        int r0 = atomicAdd(&g_deg[d.x], 1);
        int r1 = atomicAdd(&g_deg[d.y], 1);
        int r2 = atomicAdd(&g_deg[d.z], 1);
        int r3 = atomicAdd(&g_deg[d.w], 1);
        ((int4*)g_rank)[e] = make_int4(r0, r1, r2, r3);
    }
}

// ---- fused single-pass exclusive scan (decoupled lookback) + dinv + t0 ----
__global__ __launch_bounds__(SCAN_TPB) void k_scanf(const float* __restrict__ x, int n, int E) {
    __shared__ int sd[SCAN_TPB];
    int t = threadIdx.x;
    int b = blockIdx.x;
    int i = b * SCAN_TPB + t;
    int v = (i < n) ? g_deg[i] : 0;
    sd[t] = v;
    __syncthreads();
    for (int off = 1; off < SCAN_TPB; off <<= 1) {
        int y = (t >= off) ? sd[t - off] : 0;
        __syncthreads();
        sd[t] += y;
        __syncthreads();
    }
    int incl = sd[t];
    if (t == SCAN_TPB - 1) {
        unsigned long long p = (1ULL << 63) | (unsigned long long)(unsigned)incl;
        *((volatile unsigned long long*)&g_pack[b]) = p;
    }
    int offs = 0;
    for (int p = t; p < b; p += SCAN_TPB) {
        unsigned long long w;
        do { w = *((volatile unsigned long long*)&g_pack[p]); } while (!(w >> 63));
        offs += (int)(unsigned)(w & 0xFFFFFFFFULL);
    }
    __syncthreads();
    sd[t] = offs;
    __syncthreads();
    for (int o = SCAN_TPB / 2; o > 0; o >>= 1) {
        if (t < o) sd[t] += sd[t + o];
        __syncthreads();
    }
    int blockoff = sd[0];
    if (i < n) {
        int off = blockoff + incl - v;
        g_off[i] = off;
        float dv = rsqrtf((float)(v + 1));  // +1 self loop
        g_dinv[i] = dv;
        g_t0[i] = x[i] * dv;
        if (i == 0) g_off[n] = E;
    }
}

// atomic-free fill: p = off[d] + rank[e]
__global__ void k_fill(const int* __restrict__ ei, int E) {
    int e = blockIdx.x * blockDim.x + threadIdx.x;
    if (e < E) {
        int s = ei[e];
        int d = ei[E + e];
        g_srcs[__ldg(&g_off[d]) + g_rank[e]] = s;
    }
}

// vectorized: 4 edges per thread (requires E % 4 == 0)
__global__ void k_fill4(const int* __restrict__ ei, int E, int E4) {
    int e = blockIdx.x * blockDim.x + threadIdx.x;
    if (e < E4) {
        int4 s = ((const int4*)ei)[e];
        int4 d = ((const int4*)(ei + E))[e];
        int4 r = ((const int4*)g_rank)[e];
        g_srcs[__ldg(&g_off[d.x]) + r.x] = s.x;
        g_srcs[__ldg(&g_off[d.y]) + r.y] = s.y;
        g_srcs[__ldg(&g_off[d.z]) + r.z] = s.z;
        g_srcs[__ldg(&g_off[d.w]) + r.w] = s.w;
    }
}

// ---------------- layer 1: scalar agg of t0, then t1 = fp16(dinv*relu(a*W1+b1)) ----------------
__global__ void k_l1(const float* __restrict__ W1, const float* __restrict__ b1, int n) {
    __shared__ float sw[16], sb[16];
    if (threadIdx.x < 16) { sw[threadIdx.x] = W1[threadIdx.x]; sb[threadIdx.x] = b1[threadIdx.x]; }
    __syncthreads();
    int v = blockIdx.x * blockDim.x + threadIdx.x;
    if (v >= n) return;
    float a = g_t0[v];
    int e = g_off[v], e1 = g_off[v + 1];
#pragma unroll 4
    for (; e < e1; e++) a += __ldg(&g_t0[__ldg(&g_srcs[e])]);
    float dv = g_dinv[v];
    a *= dv;
#pragma unroll
    for (int k = 0; k < 8; k++) {
        float u0 = dv * fmaxf(fmaf(a, sw[2 * k + 0], sb[2 * k + 0]), 0.f);
        float u1 = dv * fmaxf(fmaf(a, sw[2 * k + 1], sb[2 * k + 1]), 0.f);
        g_t1[v * 8 + k] = __float22half2_rn(make_float2(u0, u1));
    }
}

// ---------------- layer-2 agg d16 fp16, batch-8 MLP: g = dinv*(t1[v] + sum t1[src]) -> bufB fp32 ----------------
__global__ void k_agg2(int n) {
    int gid = blockIdx.x * blockDim.x + threadIdx.x;
    int v = gid >> 1;
    int c = gid & 1;
    if (v >= n) return;
    const uint4* tp = (const uint4*)g_t1;
    float acc[8];
    {
        uint4 hv = tp[v * 2 + c];
        float2 f0 = __half22float2(*(const __half2*)&hv.x);
        float2 f1 = __half22float2(*(const __half2*)&hv.y);
        float2 f2 = __half22float2(*(const __half2*)&hv.z);
        float2 f3 = __half22float2(*(const __half2*)&hv.w);
        acc[0] = f0.x; acc[1] = f0.y; acc[2] = f1.x; acc[3] = f1.y;
        acc[4] = f2.x; acc[5] = f2.y; acc[6] = f3.x; acc[7] = f3.y;
    }
    int e = g_off[v], e1 = g_off[v + 1];
    for (; e + 8 <= e1; e += 8) {
        int s0 = __ldg(&g_srcs[e + 0]);
        int s1 = __ldg(&g_srcs[e + 1]);
        int s2 = __ldg(&g_srcs[e + 2]);
        int s3 = __ldg(&g_srcs[e + 3]);
        int s4 = __ldg(&g_srcs[e + 4]);
        int s5 = __ldg(&g_srcs[e + 5]);
        int s6 = __ldg(&g_srcs[e + 6]);
        int s7 = __ldg(&g_srcs[e + 7]);
        uint4 a0 = __ldg(&tp[s0 * 2 + c]);
        uint4 a1 = __ldg(&tp[s1 * 2 + c]);
        uint4 a2 = __ldg(&tp[s2 * 2 + c]);
        uint4 a3 = __ldg(&tp[s3 * 2 + c]);
        uint4 a4 = __ldg(&tp[s4 * 2 + c]);
        uint4 a5 = __ldg(&tp[s5 * 2 + c]);
        uint4 a6 = __ldg(&tp[s6 * 2 + c]);
        uint4 a7 = __ldg(&tp[s7 * 2 + c]);
        hacc8(acc, a0); hacc8(acc, a1); hacc8(acc, a2); hacc8(acc, a3);
        hacc8(acc, a4); hacc8(acc, a5); hacc8(acc, a6); hacc8(acc, a7);
    }
    for (; e < e1; e++) {
        int s = __ldg(&g_srcs[e]);
        hacc8(acc, __ldg(&tp[s * 2 + c]));
    }
    float dv = g_dinv[v];
    g_bufB[v * 4 + c * 2 + 0] = make_float4(acc[0] * dv, acc[1] * dv, acc[2] * dv, acc[3] * dv);
    g_bufB[v * 4 + c * 2 + 1] = make_float4(acc[4] * dv, acc[5] * dv, acc[6] * dv, acc[7] * dv);
}

// ---------------- fused W2 + relu + W3 + dinv, HFMA2 W3 stage: g(d16) -> t3(d64 fp16) ----------------
// W3 packed as half2 in smem; z accumulated in half2 per 16-i chunk, promoted to fp32 between chunks.
__global__ __launch_bounds__(128) void k_t23(const float* __restrict__ W2,
                                             const float* __restrict__ b2,
                                             const float* __restrict__ W3, int n) {
    __shared__ float   sW2[16 * 64];
    __shared__ __half2 sW3h[64 * 32];   // [i][jp]: (W3[i][2jp], W3[i][2jp+1]); 8 KB
    __shared__ float   sb2[64];
    int t = threadIdx.x;
    for (int i = t; i < 16 * 64; i += blockDim.x) sW2[i] = W2[i];
    for (int idx = t; idx < 64 * 32; idx += blockDim.x) {
        int i = idx >> 5, jp = idx & 31;
        sW3h[idx] = __floats2half2_rn(W3[i * 64 + 2 * jp], W3[i * 64 + 2 * jp + 1]);
    }
    if (t < 64) sb2[t] = b2[t];
    __syncthreads();
    int v = blockIdx.x * blockDim.x + t;
    if (v >= n) return;
    float g[16];
#pragma unroll
    for (int j = 0; j < 4; j++) {
        float4 gg = g_bufB[v * 4 + j];
        g[4 * j] = gg.x; g[4 * j + 1] = gg.y; g[4 * j + 2] = gg.z; g[4 * j + 3] = gg.w;
    }
    float2 zf[32];
#pragma unroll
    for (int j = 0; j < 32; j++) zf[j] = make_float2(0.f, 0.f);
#pragma unroll
    for (int ch = 0; ch < 4; ch++) {
        // y-tile: 16 outputs [16ch, 16ch+16) = relu(g W2 + b2)
        float4 a[4];
#pragma unroll
        for (int q = 0; q < 4; q++) a[q] = ((const float4*)sb2)[ch * 4 + q];
#pragma unroll
        for (int k = 0; k < 16; k++) {
            float gk = g[k];
            const float4* wk = (const float4*)&sW2[k * 64 + ch * 16];
#pragma unroll
            for (int q = 0; q < 4; q++) {
                float4 w = wk[q];
                a[q].x = fmaf(gk, w.x, a[q].x); a[q].y = fmaf(gk, w.y, a[q].y);
                a[q].z = fmaf(gk, w.z, a[q].z); a[q].w = fmaf(gk, w.w, a[q].w);
            }
        }
        __half2 yb[16];
#pragma unroll
        for (int q = 0; q < 4; q++) {
            yb[4 * q + 0] = __float2half2_rn(fmaxf(a[q].x, 0.f));
            yb[4 * q + 1] = __float2half2_rn(fmaxf(a[q].y, 0.f));
            yb[4 * q + 2] = __float2half2_rn(fmaxf(a[q].z, 0.f));
            yb[4 * q + 3] = __float2half2_rn(fmaxf(a[q].w, 0.f));
        }
        // z-chunk: half2 accumulation over 16 i's
        __half2 zh[32];
        __half2 hz = __float2half2_rn(0.f);
#pragma unroll
        for (int j = 0; j < 32; j++) zh[j] = hz;
#pragma unroll
        for (int ii = 0; ii < 16; ii++) {
            const uint4* wr4 = (const uint4*)&sW3h[(ch * 16 + ii) * 32];
            __half2 yv = yb[ii];
#pragma unroll
            for (int jq = 0; jq < 8; jq++) {
                uint4 w = wr4[jq];
                zh[jq * 4 + 0] = __hfma2(yv, *(const __half2*)&w.x, zh[jq * 4 + 0]);
                zh[jq * 4 + 1] = __hfma2(yv, *(const __half2*)&w.y, zh[jq * 4 + 1]);
                zh[jq * 4 + 2] = __hfma2(yv, *(const __half2*)&w.z, zh[jq * 4 + 2]);
                zh[jq * 4 + 3] = __hfma2(yv, *(const __half2*)&w.w, zh[jq * 4 + 3]);
            }
        }
#pragma unroll
        for (int j = 0; j < 32; j++) {
            float2 f = __half22float2(zh[j]);
            zf[j].x += f.x; zf[j].y += f.y;
        }
    }
    float dv = g_dinv[v];
#pragma unroll
    for (int j = 0; j < 32; j++)
        g_bufH[v * 32 + j] = __float22half2_rn(make_float2(zf[j].x * dv, zf[j].y * dv));
}

// ---------------- d=64 fp16 agg (batch-8 MLP) + b3 + relu + W4 + group reduce + dinv ----------------
__global__ void k_agg3w4(const float* __restrict__ b3, const float* __restrict__ W4, int n) {
    __shared__ float sW4[64 * 5];
    int t = threadIdx.x;
    for (int i = t; i < 64 * 5; i += blockDim.x) sW4[i] = W4[i];
    __syncthreads();
    int gid = blockIdx.x * blockDim.x + t;
    int v = gid / 8;
    int c = gid % 8;
    if (v >= n) return;

    const uint4* hp = (const uint4*)g_bufH;
    float acc[8];
    {
        uint4 hv = hp[v * 8 + c];
        float2 f0 = __half22float2(*(const __half2*)&hv.x);
        float2 f1 = __half22float2(*(const __half2*)&hv.y);
        float2 f2 = __half22float2(*(const __half2*)&hv.z);
        float2 f3 = __half22float2(*(const __half2*)&hv.w);
        acc[0] = f0.x; acc[1] = f0.y; acc[2] = f1.x; acc[3] = f1.y;
        acc[4] = f2.x; acc[5] = f2.y; acc[6] = f3.x; acc[7] = f3.y;
    }
    int e = g_off[v], e1 = g_off[v + 1];
    for (; e + 8 <= e1; e += 8) {
        int s0 = __ldg(&g_srcs[e + 0]);
        int s1 = __ldg(&g_srcs[e + 1]);
        int s2 = __ldg(&g_srcs[e + 2]);
        int s3 = __ldg(&g_srcs[e + 3]);
        int s4 = __ldg(&g_srcs[e + 4]);
        int s5 = __ldg(&g_srcs[e + 5]);
        int s6 = __ldg(&g_srcs[e + 6]);
        int s7 = __ldg(&g_srcs[e + 7]);
        uint4 a0 = __ldg(&hp[s0 * 8 + c]);
        uint4 a1 = __ldg(&hp[s1 * 8 + c]);
        uint4 a2 = __ldg(&hp[s2 * 8 + c]);
        uint4 a3 = __ldg(&hp[s3 * 8 + c]);
        uint4 a4 = __ldg(&hp[s4 * 8 + c]);
        uint4 a5 = __ldg(&hp[s5 * 8 + c]);
        uint4 a6 = __ldg(&hp[s6 * 8 + c]);
        uint4 a7 = __ldg(&hp[s7 * 8 + c]);
        hacc8(acc, a0); hacc8(acc, a1); hacc8(acc, a2); hacc8(acc, a3);
        hacc8(acc, a4); hacc8(acc, a5); hacc8(acc, a6); hacc8(acc, a7);
    }
    for (; e < e1; e++) {
        int s = __ldg(&g_srcs[e]);
        hacc8(acc, __ldg(&hp[s * 8 + c]));
    }
    float dv = g_dinv[v];
    float4 bb0 = ((const float4*)b3)[2 * c];
    float4 bb1 = ((const float4*)b3)[2 * c + 1];
    float h[8];
    h[0] = fmaxf(fmaf(acc[0], dv, bb0.x), 0.f);
    h[1] = fmaxf(fmaf(acc[1], dv, bb0.y), 0.f);
    h[2] = fmaxf(fmaf(acc[2], dv, bb0.z), 0.f);
    h[3] = fmaxf(fmaf(acc[3], dv, bb0.w), 0.f);
    h[4] = fmaxf(fmaf(acc[4], dv, bb1.x), 0.f);
    h[5] = fmaxf(fmaf(acc[5], dv, bb1.y), 0.f);
    h[6] = fmaxf(fmaf(acc[6], dv, bb1.z), 0.f);
    h[7] = fmaxf(fmaf(acc[7], dv, bb1.w), 0.f);
    const float* w = &sW4[c * 8 * 5];
    float p[5];
#pragma unroll
    for (int j = 0; j < 5; j++) {
        float s = h[0] * w[j];
#pragma unroll
        for (int i = 1; i < 8; i++) s = fmaf(h[i], w[i * 5 + j], s);
        p[j] = s;
    }
    unsigned m = __activemask();
#pragma unroll
    for (int off = 4; off > 0; off >>= 1) {
#pragma unroll
        for (int j = 0; j < 5; j++) p[j] += __shfl_down_sync(m, p[j], off, 8);
    }
    if (c == 0) {
        g_bufB[v * 2 + 0] = make_float4(dv * p[0], dv * p[1], dv * p[2], dv * p[3]);
        g_bufB[v * 2 + 1] = make_float4(dv * p[4], 0.f, 0.f, 0.f);
    }
}

// ---------------- final d=5 agg + b4 + log_softmax ----------------
__global__ void k_final(const float* __restrict__ b4, float* __restrict__ out, int n) {
    int v = blockIdx.x * blockDim.x + threadIdx.x;
    if (v >= n) return;
    float4 a0 = g_bufB[v * 2 + 0];
    float4 a1 = g_bufB[v * 2 + 1];
    int e = g_off[v], e1 = g_off[v + 1];
#pragma unroll 4
    for (; e < e1; e++) {
        int s = __ldg(&g_srcs[e]);
        float4 t0 = __ldg(&g_bufB[s * 2 + 0]);
        float4 t1 = __ldg(&g_bufB[s * 2 + 1]);
        a0.x += t0.x; a0.y += t0.y; a0.z += t0.z; a0.w += t0.w;
        a1.x += t1.x;
    }
    float dv = g_dinv[v];
    float z[5];
    z[0] = fmaf(a0.x, dv, b4[0]);
    z[1] = fmaf(a0.y, dv, b4[1]);
    z[2] = fmaf(a0.z, dv, b4[2]);
    z[3] = fmaf(a0.w, dv, b4[3]);
    z[4] = fmaf(a1.x, dv, b4[4]);
    float mx = z[0];
#pragma unroll
    for (int j = 1; j < 5; j++) mx = fmaxf(mx, z[j]);
    float sum = 0.f;
#pragma unroll
    for (int j = 0; j < 5; j++) sum += expf(z[j] - mx);
    float l = mx + logf(sum);
#pragma unroll
    for (int j = 0; j < 5; j++) out[v * 5 + j] = z[j] - l;
}

extern "C" void kernel_launch(void* const* d_in, const int* in_sizes, int n_in,
                              void* d_out, int out_size) {
    const float* x  = (const float*)d_in[0];
    const int*   ei = (const int*)d_in[1];      // int32 (JAX x64 disabled)
    const float* W1 = (const float*)d_in[2];
    const float* b1 = (const float*)d_in[3];
    const float* W2 = (const float*)d_in[4];
    const float* b2 = (const float*)d_in[5];
    const float* W3 = (const float*)d_in[6];
    const float* b3 = (const float*)d_in[7];
    const float* W4 = (const float*)d_in[8];
    const float* b4 = (const float*)d_in[9];
    float* out = (float*)d_out;

    int N = in_sizes[0];
    int E = in_sizes[1] / 2;

    int nB  = (N + 255) / 256;
    int snb = (N + SCAN_TPB - 1) / SCAN_TPB;

    // CSR build: zero -> count(+rank) -> fused scan -> atomic-free fill
    k_zero<<<nB, 256>>>(N);
    if ((E & 3) == 0) {
        int E4 = E >> 2;
        int eB4 = (E4 + 255) / 256;
        k_count4<<<eB4, 256>>>(ei + E, E4);
        k_scanf<<<snb, SCAN_TPB>>>(x, N, E);
        k_fill4<<<eB4, 256>>>(ei, E, E4);
    } else {
        int eB = (E + 255) / 256;
        k_count<<<eB, 256>>>(ei, E);
        k_scanf<<<snb, SCAN_TPB>>>(x, N, E);
        k_fill<<<eB, 256>>>(ei, E);
    }

    // Layer 1: scalar agg + transform (1->16), fp16 out
    k_l1<<<nB, 256>>>(W1, b1, N);
    // Layer 2 agg in d=16 fp16 (before W2), batch-8 MLP
    k_agg2<<<(N * 2 + 255) / 256, 256>>>(N);
    // Fused W2+relu+W3 node transform (HFMA2 W3 stage)
    k_t23<<<(N + 127) / 128, 128>>>(W2, b2, W3, N);
    // Layer 3 agg d=64 fp16 (batch-8 MLP), fused bias/relu/W4 epilogue
    k_agg3w4<<<(N * 8 + 255) / 256, 256>>>(b3, W4, N);
    // Layer 4 agg d=5 + log_softmax
    k_final<<<nB, 256>>>(b4, out, N);
}